// round 13
// baseline (speedup 1.0000x reference)
#include <cuda_runtime.h>
#include <math.h>
#include <stdint.h>

#define BB 2
#define SS 2048
#define EE 4096
#define HQN 32
#define HKVN 8
#define DD 128
#define NROWS (BB*SS)      // 4096
#define WIN 1024
#define TQ 64
#define TK 64

// ---------------- scratch ----------------
__device__ float g_q[(size_t)NROWS * HQN * DD];
__device__ float g_k[(size_t)NROWS * HKVN * DD];
__device__ float g_v[(size_t)NROWS * HKVN * DD];
__device__ uint32_t g_xt[(size_t)NROWS * EE];
__device__ uint32_t g_wqt[(size_t)EE * HQN * DD];
__device__ uint32_t g_wkt[(size_t)EE * HKVN * DD];
__device__ uint32_t g_wvt[(size_t)EE * HKVN * DD];
__device__ uint32_t g_wot[(size_t)HQN * DD * EE];
__device__ uint32_t g_attnt[(size_t)NROWS * HQN * DD];
__device__ float g_freq[64];

// ---------------- helpers ----------------
__device__ __forceinline__ uint32_t f2tf32(float f) {
    uint32_t u;
    asm("cvt.rna.tf32.f32 %0, %1;" : "=r"(u) : "f"(f));
    return u;
}

__device__ __forceinline__ void mma_tf32(float c[4], const uint32_t a[4], const uint32_t b[2]) {
    asm volatile(
        "mma.sync.aligned.m16n8k8.row.col.f32.tf32.tf32.f32 "
        "{%0,%1,%2,%3}, {%4,%5,%6,%7}, {%8,%9}, {%0,%1,%2,%3};\n"
        : "+f"(c[0]), "+f"(c[1]), "+f"(c[2]), "+f"(c[3])
        : "r"(a[0]), "r"(a[1]), "r"(a[2]), "r"(a[3]), "r"(b[0]), "r"(b[1]));
}

__device__ __forceinline__ void cp16(void* sdst, const void* gsrc) {
    uint32_t sa = (uint32_t)__cvta_generic_to_shared(sdst);
    asm volatile("cp.async.cg.shared.global [%0], [%1], 16;\n" :: "r"(sa), "l"(gsrc));
}

// ---------------- init: rope freq table (same double math as before -> bitwise identical) ----
__global__ void init_freq_kernel()
{
    int t = threadIdx.x;
    if (t < 64) g_freq[t] = (float)exp(-(double)t * (9.210340371976184 / 64.0));
}

// ---------------- fp32 -> tf32 conversion ----------------
__global__ __launch_bounds__(256) void cvt_tf32_kernel(const float* __restrict__ in,
                                                       uint32_t* __restrict__ out)
{
    size_t i = ((size_t)blockIdx.x * 256 + threadIdx.x) * 4;
    float4 v = *(const float4*)(in + i);
    uint4 u;
    u.x = f2tf32(v.x); u.y = f2tf32(v.y); u.z = f2tf32(v.z); u.w = f2tf32(v.w);
    *(uint4*)(out + i) = u;
}

// ---------------- pipelined TF32 GEMM: 256x128 tile, 3 stages, 512 threads ----------------
#define A_ST 36
#define B_ST 136
#define A_STAGE (256 * A_ST)
#define B_STAGE (32 * B_ST)

__device__ __forceinline__ void gemm_load_stage(
    const uint32_t* __restrict__ A, const uint32_t* __restrict__ B,
    uint32_t* __restrict__ as, uint32_t* __restrict__ bs,
    int row0, int col0, int k0, int K, int N, int tid)
{
#pragma unroll
    for (int it = 0; it < 4; it++) {
        int idx = tid + it * 512;                // 2048 chunks: 256 rows x 8
        int r  = idx >> 3;
        int ch = (idx & 7) << 2;
        cp16(as + r * A_ST + ch, A + (size_t)(row0 + r) * K + k0 + ch);
    }
#pragma unroll
    for (int it = 0; it < 2; it++) {
        int idx = tid + it * 512;                // 1024 chunks: 32 rows x 32
        int r  = idx >> 5;
        int ch = (idx & 31) << 2;
        cp16(bs + r * B_ST + ch, B + (size_t)(k0 + r) * N + col0 + ch);
    }
    asm volatile("cp.async.commit_group;\n");
}

__global__ __launch_bounds__(512, 1) void gemm_tf32p_kernel(
    const uint32_t* __restrict__ A, const uint32_t* __restrict__ B, float* __restrict__ C,
    int M, int N, int K)
{
    extern __shared__ uint32_t sh[];
    uint32_t* As = sh;                       // 3 stages [256][A_ST]
    uint32_t* Bs = sh + 3 * A_STAGE;         // 3 stages [32][B_ST]

    const int tid  = threadIdx.x;
    const int warp = tid >> 5;
    const int lane = tid & 31;
    const int l4   = lane & 3;
    const int l28  = lane >> 2;

    const int m0 = (warp >> 2) * 64;         // 0..192
    const int n0 = (warp & 3) * 32;          // 0..96
    const int row0 = blockIdx.y * 256;
    const int col0 = blockIdx.x * 128;

    float cacc[4][4][4];
#pragma unroll
    for (int mt = 0; mt < 4; mt++)
#pragma unroll
        for (int nt = 0; nt < 4; nt++)
#pragma unroll
            for (int r = 0; r < 4; r++) cacc[mt][nt][r] = 0.0f;

    const int T = K >> 5;
    gemm_load_stage(A, B, As, Bs, row0, col0, 0, K, N, tid);
    gemm_load_stage(A, B, As + A_STAGE, Bs + B_STAGE, row0, col0, 32, K, N, tid);

    for (int kt = 0; kt < T; kt++) {
        if (kt + 2 < T) {
            int st = (kt + 2) % 3;
            gemm_load_stage(A, B, As + st * A_STAGE, Bs + st * B_STAGE,
                            row0, col0, (kt + 2) << 5, K, N, tid);
            asm volatile("cp.async.wait_group 2;\n");
        } else {
            asm volatile("cp.async.wait_group 0;\n");
        }
        __syncthreads();

        const uint32_t* as = As + (kt % 3) * A_STAGE;
        const uint32_t* bs = Bs + (kt % 3) * B_STAGE;

#pragma unroll
        for (int ks = 0; ks < 32; ks += 8) {
            uint32_t bf[4][2];
#pragma unroll
            for (int nt = 0; nt < 4; nt++) {
                int n = n0 + nt * 8 + l28;
                bf[nt][0] = bs[(ks + l4) * B_ST + n];
                bf[nt][1] = bs[(ks + 4 + l4) * B_ST + n];
            }
#pragma unroll
            for (int mt = 0; mt < 4; mt++) {
                int m = m0 + mt * 16 + l28;
                uint32_t af[4];
                af[0] = as[m * A_ST + ks + l4];
                af[1] = as[(m + 8) * A_ST + ks + l4];
                af[2] = as[m * A_ST + ks + 4 + l4];
                af[3] = as[(m + 8) * A_ST + ks + 4 + l4];
#pragma unroll
                for (int nt = 0; nt < 4; nt++)
                    mma_tf32(cacc[mt][nt], af, bf[nt]);
            }
        }
        __syncthreads();
    }

#pragma unroll
    for (int mt = 0; mt < 4; mt++) {
#pragma unroll
        for (int nt = 0; nt < 4; nt++) {
            int row = row0 + m0 + mt * 16 + l28;
            int col = col0 + n0 + nt * 8 + (l4 << 1);
            *(float2*)(C + (size_t)row * N + col)       = make_float2(cacc[mt][nt][0], cacc[mt][nt][1]);
            *(float2*)(C + (size_t)(row + 8) * N + col) = make_float2(cacc[mt][nt][2], cacc[mt][nt][3]);
        }
    }
}

// ---------------- l2norm + RoPE: warp per row, table-driven freqs ----------------
__global__ __launch_bounds__(256) void norm_rope2_kernel(float* __restrict__ data, int H, int isQ)
{
    const int gw   = blockIdx.x * 8 + (threadIdx.x >> 5);
    const int lane = threadIdx.x & 31;
    const int s    = (gw / H) % SS;
    float* ptr = data + (size_t)gw * DD;

    float v0 = ptr[lane];
    float v1 = ptr[lane + 32];
    float v2 = ptr[lane + 64];
    float v3 = ptr[lane + 96];

    float ss = v0 * v0 + v1 * v1 + v2 * v2 + v3 * v3;
#pragma unroll
    for (int off = 16; off > 0; off >>= 1)
        ss += __shfl_xor_sync(0xffffffffu, ss, off);

    float inv = rsqrtf(ss * (1.0f / DD) + 1e-6f);
    v0 *= inv; v1 *= inv; v2 *= inv; v3 *= inv;

    float freq0 = g_freq[lane];
    float freq1 = g_freq[lane + 32];
    float s0, c0, s1, c1;
    sincosf((float)s * freq0, &s0, &c0);
    sincosf((float)s * freq1, &s1, &c1);

    float o0 = v0 * c0 - v2 * s0;
    float o2 = v2 * c0 + v0 * s0;
    float o1 = v1 * c1 - v3 * s1;
    float o3 = v3 * c1 + v1 * s1;

    if (isQ) {
        float asc = logf(floorf(((float)s + 1.0f) / 8192.0f) + 1.0f) * 0.1f + 1.0f;
        float sc = 0.08838834764831845f * asc;
        o0 *= sc; o1 *= sc; o2 *= sc; o3 *= sc;
    }
    ptr[lane]      = o0;
    ptr[lane + 32] = o1;
    ptr[lane + 64] = o2;
    ptr[lane + 96] = o3;
}

// ---------------- tensor-core flash attention (epilogue writes tf32) ----------------
#define QK_STRIDE 132
#define V_STRIDE  136
#define P_STRIDE  68
__global__ __launch_bounds__(256) void attn_tc_kernel()
{
    extern __shared__ uint32_t smu[];
    uint32_t* sQ = smu;
    uint32_t* sK = sQ + 64 * QK_STRIDE;
    uint32_t* sV = sK + 64 * QK_STRIDE;
    float*    sP = (float*)(sV + 64 * V_STRIDE);
    float*    sM = sP + 64 * P_STRIDE;
    float*    sSum = sM + 64;
    float*    sAlpha = sSum + 64;

    const int b  = blockIdx.z;
    const int h  = blockIdx.y;
    const int q0 = blockIdx.x * TQ;
    const int hk = h / (HQN / HKVN);

    const int tid  = threadIdx.x;
    const int warp = tid >> 5;
    const int lane = tid & 31;
    const int l4   = lane & 3;
    const int l28  = lane >> 2;

    const int wm = warp >> 2;
    const int wn = warp & 3;

#pragma unroll
    for (int i = 0; i < 8; i++) {
        int idx = tid + i * 256;
        int r  = idx >> 5;
        int c4 = (idx & 31) << 2;
        float4 qv = *(const float4*)&g_q[(((size_t)(b * SS + q0 + r)) * HQN + h) * DD + c4];
        sQ[r * QK_STRIDE + c4 + 0] = f2tf32(qv.x);
        sQ[r * QK_STRIDE + c4 + 1] = f2tf32(qv.y);
        sQ[r * QK_STRIDE + c4 + 2] = f2tf32(qv.z);
        sQ[r * QK_STRIDE + c4 + 3] = f2tf32(qv.w);
    }
    if (tid < 64) { sM[tid] = -30000.0f; sSum[tid] = 0.0f; }

    float o[2][4][4];
#pragma unroll
    for (int mt = 0; mt < 2; mt++)
#pragma unroll
        for (int nt = 0; nt < 4; nt++)
#pragma unroll
            for (int r = 0; r < 4; r++) o[mt][nt][r] = 0.0f;

    int jlo = q0 - (WIN - 1); if (jlo < 0) jlo = 0;
    int jt0 = (jlo / TK) * TK;

    for (int jt = jt0; jt <= q0; jt += TK) {
        __syncthreads();

#pragma unroll
        for (int i = 0; i < 8; i++) {
            int idx = tid + i * 256;
            int r  = idx >> 5;
            int c4 = (idx & 31) << 2;
            size_t gbase = (((size_t)(b * SS + jt + r)) * HKVN + hk) * DD + c4;
            float4 kv = *(const float4*)&g_k[gbase];
            sK[r * QK_STRIDE + c4 + 0] = f2tf32(kv.x);
            sK[r * QK_STRIDE + c4 + 1] = f2tf32(kv.y);
            sK[r * QK_STRIDE + c4 + 2] = f2tf32(kv.z);
            sK[r * QK_STRIDE + c4 + 3] = f2tf32(kv.w);
            float4 vv = *(const float4*)&g_v[gbase];
            sV[r * V_STRIDE + c4 + 0] = f2tf32(vv.x);
            sV[r * V_STRIDE + c4 + 1] = f2tf32(vv.y);
            sV[r * V_STRIDE + c4 + 2] = f2tf32(vv.z);
            sV[r * V_STRIDE + c4 + 3] = f2tf32(vv.w);
        }
        __syncthreads();

        {
            const int sm0 = wm * 32;
            const int sn0 = wn * 16;
            float acc[2][2][4];
#pragma unroll
            for (int mt = 0; mt < 2; mt++)
#pragma unroll
                for (int nt = 0; nt < 2; nt++)
#pragma unroll
                    for (int r = 0; r < 4; r++) acc[mt][nt][r] = 0.0f;

#pragma unroll
            for (int ks = 0; ks < 16; ks++) {
                const int k0 = ks * 8;
                uint32_t bf[2][2];
#pragma unroll
                for (int nt = 0; nt < 2; nt++) {
                    int n = sn0 + nt * 8 + l28;
                    bf[nt][0] = sK[n * QK_STRIDE + k0 + l4];
                    bf[nt][1] = sK[n * QK_STRIDE + k0 + 4 + l4];
                }
#pragma unroll
                for (int mt = 0; mt < 2; mt++) {
                    int m = sm0 + mt * 16 + l28;
                    uint32_t af[4];
                    af[0] = sQ[m * QK_STRIDE + k0 + l4];
                    af[1] = sQ[(m + 8) * QK_STRIDE + k0 + l4];
                    af[2] = sQ[m * QK_STRIDE + k0 + 4 + l4];
                    af[3] = sQ[(m + 8) * QK_STRIDE + k0 + 4 + l4];
#pragma unroll
                    for (int nt = 0; nt < 2; nt++)
                        mma_tf32(acc[mt][nt], af, bf[nt]);
                }
            }

#pragma unroll
            for (int mt = 0; mt < 2; mt++) {
#pragma unroll
                for (int nt = 0; nt < 2; nt++) {
#pragma unroll
                    for (int r = 0; r < 4; r++) {
                        int lrow = sm0 + mt * 16 + l28 + ((r >> 1) << 3);
                        int lcol = sn0 + nt * 8 + (l4 << 1) + (r & 1);
                        int i = q0 + lrow;
                        int j = jt + lcol;
                        float lg = 50.0f * tanhf(acc[mt][nt][r] * 0.02f);
                        bool valid = (j <= i) && (i - j < WIN);
                        sP[lrow * P_STRIDE + lcol] = valid ? lg : -30000.0f;
                    }
                }
            }
        }
        __syncthreads();

        if (tid < 64) {
            float tm = -30000.0f;
            for (int jj = 0; jj < TK; jj++) {
                int j = (jj + tid) & 63;
                tm = fmaxf(tm, sP[tid * P_STRIDE + j]);
            }
            float mo = sM[tid];
            float mn = fmaxf(mo, tm);
            float alpha = __expf(mo - mn);
            float rs = 0.0f;
            for (int jj = 0; jj < TK; jj++) {
                int j = (jj + tid) & 63;
                float lv = sP[tid * P_STRIDE + j];
                float p = (lv > -20000.0f) ? __expf(lv - mn) : 0.0f;
                sP[tid * P_STRIDE + j] = p;
                rs += p;
            }
            sSum[tid] = sSum[tid] * alpha + rs;
            sM[tid] = mn;
            sAlpha[tid] = alpha;
        }
        __syncthreads();

        {
            const int om0 = wm * 32;
            const int on0 = wn * 32;
#pragma unroll
            for (int mt = 0; mt < 2; mt++) {
                float a_lo = sAlpha[om0 + mt * 16 + l28];
                float a_hi = sAlpha[om0 + mt * 16 + l28 + 8];
#pragma unroll
                for (int nt = 0; nt < 4; nt++) {
                    o[mt][nt][0] *= a_lo; o[mt][nt][1] *= a_lo;
                    o[mt][nt][2] *= a_hi; o[mt][nt][3] *= a_hi;
                }
            }
#pragma unroll
            for (int ks = 0; ks < 8; ks++) {
                const int jb = ks * 8;
                uint32_t bf[4][2];
#pragma unroll
                for (int nt = 0; nt < 4; nt++) {
                    int n = on0 + nt * 8 + l28;
                    bf[nt][0] = sV[(jb + l4) * V_STRIDE + n];
                    bf[nt][1] = sV[(jb + 4 + l4) * V_STRIDE + n];
                }
#pragma unroll
                for (int mt = 0; mt < 2; mt++) {
                    int m = om0 + mt * 16 + l28;
                    uint32_t af[4];
                    af[0] = f2tf32(sP[m * P_STRIDE + jb + l4]);
                    af[1] = f2tf32(sP[(m + 8) * P_STRIDE + jb + l4]);
                    af[2] = f2tf32(sP[m * P_STRIDE + jb + 4 + l4]);
                    af[3] = f2tf32(sP[(m + 8) * P_STRIDE + jb + 4 + l4]);
#pragma unroll
                    for (int nt = 0; nt < 4; nt++)
                        mma_tf32(o[mt][nt], af, bf[nt]);
                }
            }
        }
    }

    // epilogue: normalize and store directly as tf32 (A operand of out-projection)
    {
        const int om0 = wm * 32;
        const int on0 = wn * 32;
#pragma unroll
        for (int mt = 0; mt < 2; mt++) {
            int rlo = om0 + mt * 16 + l28;
            float inv_lo = 1.0f / sSum[rlo];
            float inv_hi = 1.0f / sSum[rlo + 8];
#pragma unroll
            for (int nt = 0; nt < 4; nt++) {
                int col = on0 + nt * 8 + (l4 << 1);
                size_t base_lo = (((size_t)(b * SS + q0 + rlo)) * HQN + h) * DD + col;
                size_t base_hi = (((size_t)(b * SS + q0 + rlo + 8)) * HQN + h) * DD + col;
                uint2 ulo, uhi;
                ulo.x = f2tf32(o[mt][nt][0] * inv_lo);
                ulo.y = f2tf32(o[mt][nt][1] * inv_lo);
                uhi.x = f2tf32(o[mt][nt][2] * inv_hi);
                uhi.y = f2tf32(o[mt][nt][3] * inv_hi);
                *(uint2*)&g_attnt[base_lo] = ulo;
                *(uint2*)&g_attnt[base_hi] = uhi;
            }
        }
    }
}

// ---------------- launch ----------------
extern "C" void kernel_launch(void* const* d_in, const int* in_sizes, int n_in,
                              void* d_out, int out_size)
{
    const float* x  = (const float*)d_in[0];
    const float* Wq = (const float*)d_in[1];
    const float* Wk = (const float*)d_in[2];
    const float* Wv = (const float*)d_in[3];
    const float* Wo = (const float*)d_in[4];
    float* out = (float*)d_out;

    float *q, *k, *v;
    uint32_t *xt, *wqt, *wkt, *wvt, *wot, *attnt;
    cudaGetSymbolAddress((void**)&q,    g_q);
    cudaGetSymbolAddress((void**)&k,    g_k);
    cudaGetSymbolAddress((void**)&v,    g_v);
    cudaGetSymbolAddress((void**)&xt,   g_xt);
    cudaGetSymbolAddress((void**)&wqt,  g_wqt);
    cudaGetSymbolAddress((void**)&wkt,  g_wkt);
    cudaGetSymbolAddress((void**)&wvt,  g_wvt);
    cudaGetSymbolAddress((void**)&wot,  g_wot);
    cudaGetSymbolAddress((void**)&attnt,g_attnt);

    const size_t NBIG = (size_t)NROWS * EE;
    const size_t NSML = (size_t)EE * HKVN * DD;

    init_freq_kernel<<<1, 64>>>();

    cvt_tf32_kernel<<<(int)(NBIG / 1024), 256>>>(x,  xt);
    cvt_tf32_kernel<<<(int)(NBIG / 1024), 256>>>(Wq, wqt);
    cvt_tf32_kernel<<<(int)(NSML / 1024), 256>>>(Wk, wkt);
    cvt_tf32_kernel<<<(int)(NSML / 1024), 256>>>(Wv, wvt);
    cvt_tf32_kernel<<<(int)(NBIG / 1024), 256>>>(Wo, wot);

    const int gemm_smem = 3 * (A_STAGE + B_STAGE) * 4;   // 162816
    cudaFuncSetAttribute(gemm_tf32p_kernel, cudaFuncAttributeMaxDynamicSharedMemorySize, gemm_smem);

    // QKV projections (256-row tiles)
    gemm_tf32p_kernel<<<dim3(HQN * DD / 128, NROWS / 256), 512, gemm_smem>>>(xt, wqt, q, NROWS, HQN * DD, EE);
    gemm_tf32p_kernel<<<dim3(HKVN * DD / 128, NROWS / 256), 512, gemm_smem>>>(xt, wkt, k, NROWS, HKVN * DD, EE);
    gemm_tf32p_kernel<<<dim3(HKVN * DD / 128, NROWS / 256), 512, gemm_smem>>>(xt, wvt, v, NROWS, HKVN * DD, EE);

    // l2norm + rope (table-driven freqs)
    norm_rope2_kernel<<<NROWS * HQN / 8, 256>>>(q, HQN, 1);
    norm_rope2_kernel<<<NROWS * HKVN / 8, 256>>>(k, HKVN, 0);

    // attention (tensor cores; writes tf32)
    const int att_smem = (64 * QK_STRIDE * 2 + 64 * V_STRIDE) * 4 + (64 * P_STRIDE + 3 * 64) * 4;
    cudaFuncSetAttribute(attn_tc_kernel, cudaFuncAttributeMaxDynamicSharedMemorySize, att_smem);
    attn_tc_kernel<<<dim3(SS / TQ, HQN, BB), 256, att_smem>>>();

    // output projection
    gemm_tf32p_kernel<<<dim3(EE / 128, NROWS / 256), 512, gemm_smem>>>(attnt, wot, out, NROWS, EE, HQN * DD);
}

// round 14
// speedup vs baseline: 1.2526x; 1.2526x over previous
#include <cuda_runtime.h>
#include <math.h>
#include <stdint.h>

#define BB 2
#define SS 2048
#define EE 4096
#define HQN 32
#define HKVN 8
#define DD 128
#define NROWS (BB*SS)      // 4096
#define WIN 1024
#define TQ 128
#define TK 64

// ---------------- scratch ----------------
__device__ float g_q[(size_t)NROWS * HQN * DD];
__device__ float g_k[(size_t)NROWS * HKVN * DD];
__device__ float g_v[(size_t)NROWS * HKVN * DD];
__device__ uint32_t g_xt[(size_t)NROWS * EE];
__device__ uint32_t g_wqt[(size_t)EE * HQN * DD];
__device__ uint32_t g_wkt[(size_t)EE * HKVN * DD];
__device__ uint32_t g_wvt[(size_t)EE * HKVN * DD];
__device__ uint32_t g_wot[(size_t)HQN * DD * EE];
__device__ uint32_t g_attnt[(size_t)NROWS * HQN * DD];
__device__ float g_freq[64];

// ---------------- helpers ----------------
__device__ __forceinline__ uint32_t f2tf32(float f) {
    uint32_t u;
    asm("cvt.rna.tf32.f32 %0, %1;" : "=r"(u) : "f"(f));
    return u;
}

__device__ __forceinline__ void mma_tf32(float c[4], const uint32_t a[4], const uint32_t b[2]) {
    asm volatile(
        "mma.sync.aligned.m16n8k8.row.col.f32.tf32.tf32.f32 "
        "{%0,%1,%2,%3}, {%4,%5,%6,%7}, {%8,%9}, {%0,%1,%2,%3};\n"
        : "+f"(c[0]), "+f"(c[1]), "+f"(c[2]), "+f"(c[3])
        : "r"(a[0]), "r"(a[1]), "r"(a[2]), "r"(a[3]), "r"(b[0]), "r"(b[1]));
}

__device__ __forceinline__ void cp16(void* sdst, const void* gsrc) {
    uint32_t sa = (uint32_t)__cvta_generic_to_shared(sdst);
    asm volatile("cp.async.cg.shared.global [%0], [%1], 16;\n" :: "r"(sa), "l"(gsrc));
}

// ---------------- init: rope freq table ----------------
__global__ void init_freq_kernel()
{
    int t = threadIdx.x;
    if (t < 64) g_freq[t] = (float)exp(-(double)t * (9.210340371976184 / 64.0));
}

// ---------------- fp32 -> tf32 conversion ----------------
__global__ __launch_bounds__(256) void cvt_tf32_kernel(const float* __restrict__ in,
                                                       uint32_t* __restrict__ out)
{
    size_t i = ((size_t)blockIdx.x * 256 + threadIdx.x) * 4;
    float4 v = *(const float4*)(in + i);
    uint4 u;
    u.x = f2tf32(v.x); u.y = f2tf32(v.y); u.z = f2tf32(v.z); u.w = f2tf32(v.w);
    *(uint4*)(out + i) = u;
}

// ---------------- pipelined TF32 GEMM (round-12 config: 128x128, 2-stage, 2 CTA/SM) ----------
#define A_ST 36
#define B_ST 136
#define A_STAGE (128 * A_ST)
#define B_STAGE (32 * B_ST)

__device__ __forceinline__ void gemm_load_stage(
    const uint32_t* __restrict__ A, const uint32_t* __restrict__ B,
    uint32_t* __restrict__ as, uint32_t* __restrict__ bs,
    int row0, int col0, int k0, int K, int N, int tid)
{
#pragma unroll
    for (int it = 0; it < 4; it++) {
        int idx = tid + it * 256;                // 1024 chunks: 128 rows x 8
        int r  = idx >> 3;
        int ch = (idx & 7) << 2;
        cp16(as + r * A_ST + ch, A + (size_t)(row0 + r) * K + k0 + ch);
    }
#pragma unroll
    for (int it = 0; it < 4; it++) {
        int idx = tid + it * 256;                // 1024 chunks: 32 rows x 32
        int r  = idx >> 5;
        int ch = (idx & 31) << 2;
        cp16(bs + r * B_ST + ch, B + (size_t)(k0 + r) * N + col0 + ch);
    }
    asm volatile("cp.async.commit_group;\n");
}

__global__ __launch_bounds__(256, 2) void gemm_tf32p_kernel(
    const uint32_t* __restrict__ A, const uint32_t* __restrict__ B, float* __restrict__ C,
    int M, int N, int K)
{
    extern __shared__ uint32_t sh[];
    uint32_t* As = sh;
    uint32_t* Bs = sh + 2 * A_STAGE;

    const int tid  = threadIdx.x;
    const int warp = tid >> 5;
    const int lane = tid & 31;
    const int l4   = lane & 3;
    const int l28  = lane >> 2;

    const int m0 = (warp >> 2) * 64;
    const int n0 = (warp & 3) * 32;
    const int row0 = blockIdx.y * 128;
    const int col0 = blockIdx.x * 128;

    float cacc[4][4][4];
#pragma unroll
    for (int mt = 0; mt < 4; mt++)
#pragma unroll
        for (int nt = 0; nt < 4; nt++)
#pragma unroll
            for (int r = 0; r < 4; r++) cacc[mt][nt][r] = 0.0f;

    const int T = K >> 5;
    gemm_load_stage(A, B, As, Bs, row0, col0, 0, K, N, tid);

    for (int kt = 0; kt < T; kt++) {
        if (kt + 1 < T) {
            gemm_load_stage(A, B, As + ((kt + 1) & 1) * A_STAGE, Bs + ((kt + 1) & 1) * B_STAGE,
                            row0, col0, (kt + 1) << 5, K, N, tid);
            asm volatile("cp.async.wait_group 1;\n");
        } else {
            asm volatile("cp.async.wait_group 0;\n");
        }
        __syncthreads();

        const uint32_t* as = As + (kt & 1) * A_STAGE;
        const uint32_t* bs = Bs + (kt & 1) * B_STAGE;

#pragma unroll
        for (int ks = 0; ks < 32; ks += 8) {
            uint32_t bf[4][2];
#pragma unroll
            for (int nt = 0; nt < 4; nt++) {
                int n = n0 + nt * 8 + l28;
                bf[nt][0] = bs[(ks + l4) * B_ST + n];
                bf[nt][1] = bs[(ks + 4 + l4) * B_ST + n];
            }
#pragma unroll
            for (int mt = 0; mt < 4; mt++) {
                int m = m0 + mt * 16 + l28;
                uint32_t af[4];
                af[0] = as[m * A_ST + ks + l4];
                af[1] = as[(m + 8) * A_ST + ks + l4];
                af[2] = as[m * A_ST + ks + 4 + l4];
                af[3] = as[(m + 8) * A_ST + ks + 4 + l4];
#pragma unroll
                for (int nt = 0; nt < 4; nt++)
                    mma_tf32(cacc[mt][nt], af, bf[nt]);
            }
        }
        __syncthreads();
    }

#pragma unroll
    for (int mt = 0; mt < 4; mt++) {
#pragma unroll
        for (int nt = 0; nt < 4; nt++) {
            int row = row0 + m0 + mt * 16 + l28;
            int col = col0 + n0 + nt * 8 + (l4 << 1);
            *(float2*)(C + (size_t)row * N + col)       = make_float2(cacc[mt][nt][0], cacc[mt][nt][1]);
            *(float2*)(C + (size_t)(row + 8) * N + col) = make_float2(cacc[mt][nt][2], cacc[mt][nt][3]);
        }
    }
}

// ---------------- l2norm + RoPE: warp per row, table freqs ----------------
__global__ __launch_bounds__(256) void norm_rope2_kernel(float* __restrict__ data, int H, int isQ)
{
    const int gw   = blockIdx.x * 8 + (threadIdx.x >> 5);
    const int lane = threadIdx.x & 31;
    const int s    = (gw / H) % SS;
    float* ptr = data + (size_t)gw * DD;

    float v0 = ptr[lane];
    float v1 = ptr[lane + 32];
    float v2 = ptr[lane + 64];
    float v3 = ptr[lane + 96];

    float ss = v0 * v0 + v1 * v1 + v2 * v2 + v3 * v3;
#pragma unroll
    for (int off = 16; off > 0; off >>= 1)
        ss += __shfl_xor_sync(0xffffffffu, ss, off);

    float inv = rsqrtf(ss * (1.0f / DD) + 1e-6f);
    v0 *= inv; v1 *= inv; v2 *= inv; v3 *= inv;

    float freq0 = g_freq[lane];
    float freq1 = g_freq[lane + 32];
    float s0, c0, s1, c1;
    sincosf((float)s * freq0, &s0, &c0);
    sincosf((float)s * freq1, &s1, &c1);

    float o0 = v0 * c0 - v2 * s0;
    float o2 = v2 * c0 + v0 * s0;
    float o1 = v1 * c1 - v3 * s1;
    float o3 = v3 * c1 + v1 * s1;

    if (isQ) {
        float asc = logf(floorf(((float)s + 1.0f) / 8192.0f) + 1.0f) * 0.1f + 1.0f;
        float sc = 0.08838834764831845f * asc;
        o0 *= sc; o1 *= sc; o2 *= sc; o3 *= sc;
    }
    ptr[lane]      = o0;
    ptr[lane + 32] = o1;
    ptr[lane + 64] = o2;
    ptr[lane + 96] = o3;
}

// ---------------- tensor-core flash attention: TQ=128, tf32 epilogue ----------------
// grid (SS/128, HQN, BB), 256 threads = 8 warps as wm(4) x wn(2).
#define QK_STRIDE 132
#define V_STRIDE  136
#define P_STRIDE  68
__global__ __launch_bounds__(256) void attn_tc_kernel()
{
    extern __shared__ uint32_t smu[];
    uint32_t* sQ = smu;                         // 128 x 132
    uint32_t* sK = sQ + 128 * QK_STRIDE;        // 64 x 132
    uint32_t* sV = sK + 64 * QK_STRIDE;         // 64 x 136
    float*    sP = (float*)(sV + 64 * V_STRIDE);// 128 x 68
    float*    sM = sP + 128 * P_STRIDE;         // 128
    float*    sSum = sM + 128;                  // 128
    float*    sAlpha = sSum + 128;              // 128

    const int b  = blockIdx.z;
    const int h  = blockIdx.y;
    const int q0 = blockIdx.x * TQ;
    const int hk = h / (HQN / HKVN);

    const int tid  = threadIdx.x;
    const int warp = tid >> 5;
    const int lane = tid & 31;
    const int l4   = lane & 3;
    const int l28  = lane >> 2;

    const int wm = warp >> 1;        // 0..3 (32-row group)
    const int wn = warp & 1;         // 0..1

    // load Q tile 128x128 (cvt to tf32)
#pragma unroll
    for (int i = 0; i < 16; i++) {
        int idx = tid + i * 256;                  // 4096 float4
        int r  = idx >> 5;
        int c4 = (idx & 31) << 2;
        float4 qv = *(const float4*)&g_q[(((size_t)(b * SS + q0 + r)) * HQN + h) * DD + c4];
        sQ[r * QK_STRIDE + c4 + 0] = f2tf32(qv.x);
        sQ[r * QK_STRIDE + c4 + 1] = f2tf32(qv.y);
        sQ[r * QK_STRIDE + c4 + 2] = f2tf32(qv.z);
        sQ[r * QK_STRIDE + c4 + 3] = f2tf32(qv.w);
    }
    if (tid < 128) { sM[tid] = -30000.0f; sSum[tid] = 0.0f; }

    // O accumulators: warp tile 32(m) x 64(n): mt(2) x nt(8)
    float o[2][8][4];
#pragma unroll
    for (int mt = 0; mt < 2; mt++)
#pragma unroll
        for (int nt = 0; nt < 8; nt++)
#pragma unroll
            for (int r = 0; r < 4; r++) o[mt][nt][r] = 0.0f;

    int jlo = q0 - (WIN - 1); if (jlo < 0) jlo = 0;
    int jt0 = (jlo / TK) * TK;
    int jtmax = q0 + TQ - TK;        // last key tile needed (keys up to q0+127)

    for (int jt = jt0; jt <= jtmax; jt += TK) {
        __syncthreads();

        // load K, V tiles 64x128 (cvt to tf32)
#pragma unroll
        for (int i = 0; i < 8; i++) {
            int idx = tid + i * 256;
            int r  = idx >> 5;
            int c4 = (idx & 31) << 2;
            size_t gbase = (((size_t)(b * SS + jt + r)) * HKVN + hk) * DD + c4;
            float4 kv = *(const float4*)&g_k[gbase];
            sK[r * QK_STRIDE + c4 + 0] = f2tf32(kv.x);
            sK[r * QK_STRIDE + c4 + 1] = f2tf32(kv.y);
            sK[r * QK_STRIDE + c4 + 2] = f2tf32(kv.z);
            sK[r * QK_STRIDE + c4 + 3] = f2tf32(kv.w);
            float4 vv = *(const float4*)&g_v[gbase];
            sV[r * V_STRIDE + c4 + 0] = f2tf32(vv.x);
            sV[r * V_STRIDE + c4 + 1] = f2tf32(vv.y);
            sV[r * V_STRIDE + c4 + 2] = f2tf32(vv.z);
            sV[r * V_STRIDE + c4 + 3] = f2tf32(vv.w);
        }
        __syncthreads();

        // ---- QK^T: warp computes S[32 x 32] at (wm*32, wn*32) ----
        {
            const int sm0 = wm * 32;
            const int sn0 = wn * 32;
            float acc[2][4][4];
#pragma unroll
            for (int mt = 0; mt < 2; mt++)
#pragma unroll
                for (int nt = 0; nt < 4; nt++)
#pragma unroll
                    for (int r = 0; r < 4; r++) acc[mt][nt][r] = 0.0f;

#pragma unroll
            for (int ks = 0; ks < 16; ks++) {
                const int k0 = ks * 8;
                uint32_t bf[4][2];
#pragma unroll
                for (int nt = 0; nt < 4; nt++) {
                    int n = sn0 + nt * 8 + l28;
                    bf[nt][0] = sK[n * QK_STRIDE + k0 + l4];
                    bf[nt][1] = sK[n * QK_STRIDE + k0 + 4 + l4];
                }
#pragma unroll
                for (int mt = 0; mt < 2; mt++) {
                    int m = sm0 + mt * 16 + l28;
                    uint32_t af[4];
                    af[0] = sQ[m * QK_STRIDE + k0 + l4];
                    af[1] = sQ[(m + 8) * QK_STRIDE + k0 + l4];
                    af[2] = sQ[m * QK_STRIDE + k0 + 4 + l4];
                    af[3] = sQ[(m + 8) * QK_STRIDE + k0 + 4 + l4];
#pragma unroll
                    for (int nt = 0; nt < 4; nt++)
                        mma_tf32(acc[mt][nt], af, bf[nt]);
                }
            }

            // softcap + mask -> sP
#pragma unroll
            for (int mt = 0; mt < 2; mt++) {
#pragma unroll
                for (int nt = 0; nt < 4; nt++) {
#pragma unroll
                    for (int r = 0; r < 4; r++) {
                        int lrow = sm0 + mt * 16 + l28 + ((r >> 1) << 3);
                        int lcol = sn0 + nt * 8 + (l4 << 1) + (r & 1);
                        int i = q0 + lrow;
                        int j = jt + lcol;
                        float lg = 50.0f * tanhf(acc[mt][nt][r] * 0.02f);
                        bool valid = (j <= i) && (i - j < WIN);
                        sP[lrow * P_STRIDE + lcol] = valid ? lg : -30000.0f;
                    }
                }
            }
        }
        __syncthreads();

        // ---- online softmax (thread t owns row t, t < 128) ----
        if (tid < 128) {
            float tm = -30000.0f;
            for (int jj = 0; jj < TK; jj++) {
                int j = (jj + tid) & 63;
                tm = fmaxf(tm, sP[tid * P_STRIDE + j]);
            }
            float mo = sM[tid];
            float mn = fmaxf(mo, tm);
            float alpha = __expf(mo - mn);
            float rs = 0.0f;
            for (int jj = 0; jj < TK; jj++) {
                int j = (jj + tid) & 63;
                float lv = sP[tid * P_STRIDE + j];
                float p = (lv > -20000.0f) ? __expf(lv - mn) : 0.0f;
                sP[tid * P_STRIDE + j] = p;
                rs += p;
            }
            sSum[tid] = sSum[tid] * alpha + rs;
            sM[tid] = mn;
            sAlpha[tid] = alpha;
        }
        __syncthreads();

        // ---- PV: warp tile O[32 x 64] at (wm*32, wn*64) ----
        {
            const int om0 = wm * 32;
            const int on0 = wn * 64;
#pragma unroll
            for (int mt = 0; mt < 2; mt++) {
                float a_lo = sAlpha[om0 + mt * 16 + l28];
                float a_hi = sAlpha[om0 + mt * 16 + l28 + 8];
#pragma unroll
                for (int nt = 0; nt < 8; nt++) {
                    o[mt][nt][0] *= a_lo; o[mt][nt][1] *= a_lo;
                    o[mt][nt][2] *= a_hi; o[mt][nt][3] *= a_hi;
                }
            }
#pragma unroll
            for (int ks = 0; ks < 8; ks++) {
                const int jb = ks * 8;
                uint32_t bf[8][2];
#pragma unroll
                for (int nt = 0; nt < 8; nt++) {
                    int n = on0 + nt * 8 + l28;
                    bf[nt][0] = sV[(jb + l4) * V_STRIDE + n];
                    bf[nt][1] = sV[(jb + 4 + l4) * V_STRIDE + n];
                }
#pragma unroll
                for (int mt = 0; mt < 2; mt++) {
                    int m = om0 + mt * 16 + l28;
                    uint32_t af[4];
                    af[0] = f2tf32(sP[m * P_STRIDE + jb + l4]);
                    af[1] = f2tf32(sP[(m + 8) * P_STRIDE + jb + l4]);
                    af[2] = f2tf32(sP[m * P_STRIDE + jb + 4 + l4]);
                    af[3] = f2tf32(sP[(m + 8) * P_STRIDE + jb + 4 + l4]);
#pragma unroll
                    for (int nt = 0; nt < 8; nt++)
                        mma_tf32(o[mt][nt], af, bf[nt]);
                }
            }
        }
    }

    // epilogue: normalize and store tf32
    {
        const int om0 = wm * 32;
        const int on0 = wn * 64;
#pragma unroll
        for (int mt = 0; mt < 2; mt++) {
            int rlo = om0 + mt * 16 + l28;
            float inv_lo = 1.0f / sSum[rlo];
            float inv_hi = 1.0f / sSum[rlo + 8];
#pragma unroll
            for (int nt = 0; nt < 8; nt++) {
                int col = on0 + nt * 8 + (l4 << 1);
                size_t base_lo = (((size_t)(b * SS + q0 + rlo)) * HQN + h) * DD + col;
                size_t base_hi = (((size_t)(b * SS + q0 + rlo + 8)) * HQN + h) * DD + col;
                uint2 ulo, uhi;
                ulo.x = f2tf32(o[mt][nt][0] * inv_lo);
                ulo.y = f2tf32(o[mt][nt][1] * inv_lo);
                uhi.x = f2tf32(o[mt][nt][2] * inv_hi);
                uhi.y = f2tf32(o[mt][nt][3] * inv_hi);
                *(uint2*)&g_attnt[base_lo] = ulo;
                *(uint2*)&g_attnt[base_hi] = uhi;
            }
        }
    }
}

// ---------------- launch ----------------
extern "C" void kernel_launch(void* const* d_in, const int* in_sizes, int n_in,
                              void* d_out, int out_size)
{
    const float* x  = (const float*)d_in[0];
    const float* Wq = (const float*)d_in[1];
    const float* Wk = (const float*)d_in[2];
    const float* Wv = (const float*)d_in[3];
    const float* Wo = (const float*)d_in[4];
    float* out = (float*)d_out;

    float *q, *k, *v;
    uint32_t *xt, *wqt, *wkt, *wvt, *wot, *attnt;
    cudaGetSymbolAddress((void**)&q,    g_q);
    cudaGetSymbolAddress((void**)&k,    g_k);
    cudaGetSymbolAddress((void**)&v,    g_v);
    cudaGetSymbolAddress((void**)&xt,   g_xt);
    cudaGetSymbolAddress((void**)&wqt,  g_wqt);
    cudaGetSymbolAddress((void**)&wkt,  g_wkt);
    cudaGetSymbolAddress((void**)&wvt,  g_wvt);
    cudaGetSymbolAddress((void**)&wot,  g_wot);
    cudaGetSymbolAddress((void**)&attnt,g_attnt);

    const size_t NBIG = (size_t)NROWS * EE;
    const size_t NSML = (size_t)EE * HKVN * DD;

    init_freq_kernel<<<1, 64>>>();

    cvt_tf32_kernel<<<(int)(NBIG / 1024), 256>>>(x,  xt);
    cvt_tf32_kernel<<<(int)(NBIG / 1024), 256>>>(Wq, wqt);
    cvt_tf32_kernel<<<(int)(NSML / 1024), 256>>>(Wk, wkt);
    cvt_tf32_kernel<<<(int)(NSML / 1024), 256>>>(Wv, wvt);
    cvt_tf32_kernel<<<(int)(NBIG / 1024), 256>>>(Wo, wot);

    const int gemm_smem = (2 * A_STAGE + 2 * B_STAGE) * 4;   // 71680 -> 2 CTAs/SM
    cudaFuncSetAttribute(gemm_tf32p_kernel, cudaFuncAttributeMaxDynamicSharedMemorySize, gemm_smem);

    // QKV projections
    gemm_tf32p_kernel<<<dim3(HQN * DD / 128, NROWS / 128), 256, gemm_smem>>>(xt, wqt, q, NROWS, HQN * DD, EE);
    gemm_tf32p_kernel<<<dim3(HKVN * DD / 128, NROWS / 128), 256, gemm_smem>>>(xt, wkt, k, NROWS, HKVN * DD, EE);
    gemm_tf32p_kernel<<<dim3(HKVN * DD / 128, NROWS / 128), 256, gemm_smem>>>(xt, wvt, v, NROWS, HKVN * DD, EE);

    // l2norm + rope
    norm_rope2_kernel<<<NROWS * HQN / 8, 256>>>(q, HQN, 1);
    norm_rope2_kernel<<<NROWS * HKVN / 8, 256>>>(k, HKVN, 0);

    // attention (TQ=128)
    const int att_smem = (128 * QK_STRIDE + 64 * QK_STRIDE + 64 * V_STRIDE) * 4
                       + (128 * P_STRIDE + 3 * 128) * 4;    // 172544
    cudaFuncSetAttribute(attn_tc_kernel, cudaFuncAttributeMaxDynamicSharedMemorySize, att_smem);
    attn_tc_kernel<<<dim3(SS / TQ, HQN, BB), 256, att_smem>>>();

    // output projection
    gemm_tf32p_kernel<<<dim3(EE / 128, NROWS / 128), 256, gemm_smem>>>(attnt, wot, out, NROWS, EE, HQN * DD);
}

// round 15
// speedup vs baseline: 1.2793x; 1.0213x over previous
#include <cuda_runtime.h>
#include <math.h>
#include <stdint.h>

#define BB 2
#define SS 2048
#define EE 4096
#define HQN 32
#define HKVN 8
#define DD 128
#define NROWS (BB*SS)      // 4096
#define WIN 1024
#define TQ 128
#define TK 64

// ---------------- scratch ----------------
__device__ float g_q[(size_t)NROWS * HQN * DD];
__device__ float g_k[(size_t)NROWS * HKVN * DD];
__device__ float g_v[(size_t)NROWS * HKVN * DD];
__device__ uint32_t g_xt[(size_t)NROWS * EE];
__device__ uint32_t g_wqt[(size_t)EE * HQN * DD];
__device__ uint32_t g_wkt[(size_t)EE * HKVN * DD];
__device__ uint32_t g_wvt[(size_t)EE * HKVN * DD];
__device__ uint32_t g_wot[(size_t)HQN * DD * EE];
__device__ uint32_t g_attnt[(size_t)NROWS * HQN * DD];
__device__ float g_freq[64];

// ---------------- helpers ----------------
__device__ __forceinline__ uint32_t f2tf32(float f) {
    uint32_t u;
    asm("cvt.rna.tf32.f32 %0, %1;" : "=r"(u) : "f"(f));
    return u;
}

__device__ __forceinline__ void mma_tf32(float c[4], const uint32_t a[4], const uint32_t b[2]) {
    asm volatile(
        "mma.sync.aligned.m16n8k8.row.col.f32.tf32.tf32.f32 "
        "{%0,%1,%2,%3}, {%4,%5,%6,%7}, {%8,%9}, {%0,%1,%2,%3};\n"
        : "+f"(c[0]), "+f"(c[1]), "+f"(c[2]), "+f"(c[3])
        : "r"(a[0]), "r"(a[1]), "r"(a[2]), "r"(a[3]), "r"(b[0]), "r"(b[1]));
}

__device__ __forceinline__ void cp16(void* sdst, const void* gsrc) {
    uint32_t sa = (uint32_t)__cvta_generic_to_shared(sdst);
    asm volatile("cp.async.cg.shared.global [%0], [%1], 16;\n" :: "r"(sa), "l"(gsrc));
}

// ---------------- init: rope freq table ----------------
__global__ void init_freq_kernel()
{
    int t = threadIdx.x;
    if (t < 64) g_freq[t] = (float)exp(-(double)t * (9.210340371976184 / 64.0));
}

// ---------------- fp32 -> tf32 conversion ----------------
__global__ __launch_bounds__(256) void cvt_tf32_kernel(const float* __restrict__ in,
                                                       uint32_t* __restrict__ out)
{
    size_t i = ((size_t)blockIdx.x * 256 + threadIdx.x) * 4;
    float4 v = *(const float4*)(in + i);
    uint4 u;
    u.x = f2tf32(v.x); u.y = f2tf32(v.y); u.z = f2tf32(v.z); u.w = f2tf32(v.w);
    *(uint4*)(out + i) = u;
}

// ---------------- TF32 GEMM body: 128x128 tile, K-chunk 32, 3-stage, 256 thr, 2 CTA/SM ------
#define A_ST 36
#define B_ST 136
#define A_STAGE (128 * A_ST)
#define B_STAGE (32 * B_ST)
#define GEMM_SMEM (3 * (A_STAGE + B_STAGE) * 4)   // 107520 bytes -> 2 CTAs/SM

__device__ __forceinline__ void gemm_load_stage(
    const uint32_t* __restrict__ A, const uint32_t* __restrict__ B,
    uint32_t* __restrict__ as, uint32_t* __restrict__ bs,
    int row0, int col0, int k0, int K, int N, int tid)
{
#pragma unroll
    for (int it = 0; it < 4; it++) {
        int idx = tid + it * 256;                // 1024 chunks: 128 rows x 8
        int r  = idx >> 3;
        int ch = (idx & 7) << 2;
        cp16(as + r * A_ST + ch, A + (size_t)(row0 + r) * K + k0 + ch);
    }
#pragma unroll
    for (int it = 0; it < 4; it++) {
        int idx = tid + it * 256;                // 1024 chunks: 32 rows x 32
        int r  = idx >> 5;
        int ch = (idx & 31) << 2;
        cp16(bs + r * B_ST + ch, B + (size_t)(k0 + r) * N + col0 + ch);
    }
    asm volatile("cp.async.commit_group;\n");
}

__device__ __forceinline__ void gemm_body(
    const uint32_t* __restrict__ A, const uint32_t* __restrict__ B, float* __restrict__ C,
    int N, int K, int row0, int col0, uint32_t* sh, int tid)
{
    uint32_t* As = sh;
    uint32_t* Bs = sh + 3 * A_STAGE;

    const int warp = tid >> 5;
    const int lane = tid & 31;
    const int l4   = lane & 3;
    const int l28  = lane >> 2;
    const int m0 = (warp >> 2) * 64;
    const int n0 = (warp & 3) * 32;

    float cacc[4][4][4];
#pragma unroll
    for (int mt = 0; mt < 4; mt++)
#pragma unroll
        for (int nt = 0; nt < 4; nt++)
#pragma unroll
            for (int r = 0; r < 4; r++) cacc[mt][nt][r] = 0.0f;

    const int T = K >> 5;
    gemm_load_stage(A, B, As, Bs, row0, col0, 0, K, N, tid);
    gemm_load_stage(A, B, As + A_STAGE, Bs + B_STAGE, row0, col0, 32, K, N, tid);

    int st_ld = 2, st_use = 0;
    for (int kt = 0; kt < T; kt++) {
        if (kt + 2 < T) {
            gemm_load_stage(A, B, As + st_ld * A_STAGE, Bs + st_ld * B_STAGE,
                            row0, col0, (kt + 2) << 5, K, N, tid);
            if (++st_ld == 3) st_ld = 0;
            asm volatile("cp.async.wait_group 2;\n");
        } else {
            asm volatile("cp.async.wait_group 0;\n");
        }
        __syncthreads();

        const uint32_t* as = As + st_use * A_STAGE;
        const uint32_t* bs = Bs + st_use * B_STAGE;
        if (++st_use == 3) st_use = 0;

#pragma unroll
        for (int ks = 0; ks < 32; ks += 8) {
            uint32_t bf[4][2];
#pragma unroll
            for (int nt = 0; nt < 4; nt++) {
                int n = n0 + nt * 8 + l28;
                bf[nt][0] = bs[(ks + l4) * B_ST + n];
                bf[nt][1] = bs[(ks + 4 + l4) * B_ST + n];
            }
#pragma unroll
            for (int mt = 0; mt < 4; mt++) {
                int m = m0 + mt * 16 + l28;
                uint32_t af[4];
                af[0] = as[m * A_ST + ks + l4];
                af[1] = as[(m + 8) * A_ST + ks + l4];
                af[2] = as[m * A_ST + ks + 4 + l4];
                af[3] = as[(m + 8) * A_ST + ks + 4 + l4];
#pragma unroll
                for (int nt = 0; nt < 4; nt++)
                    mma_tf32(cacc[mt][nt], af, bf[nt]);
            }
        }
        __syncthreads();
    }

#pragma unroll
    for (int mt = 0; mt < 4; mt++) {
#pragma unroll
        for (int nt = 0; nt < 4; nt++) {
            int row = row0 + m0 + mt * 16 + l28;
            int col = col0 + n0 + nt * 8 + (l4 << 1);
            *(float2*)(C + (size_t)row * N + col)       = make_float2(cacc[mt][nt][0], cacc[mt][nt][1]);
            *(float2*)(C + (size_t)(row + 8) * N + col) = make_float2(cacc[mt][nt][2], cacc[mt][nt][3]);
        }
    }
}

// plain GEMM (used for output projection)
__global__ __launch_bounds__(256, 2) void gemm_tf32p_kernel(
    const uint32_t* __restrict__ A, const uint32_t* __restrict__ B, float* __restrict__ C,
    int M, int N, int K)
{
    extern __shared__ uint32_t sh[];
    gemm_body(A, B, C, N, K, blockIdx.y * 128, blockIdx.x * 128, sh, threadIdx.x);
}

// fused QKV GEMM: one launch, B/C selected per column block
// blockIdx.x: [0,32) -> Wq/q, [32,40) -> Wk/k, [40,48) -> Wv/v
__global__ __launch_bounds__(256, 2) void qkv_gemm_kernel(
    const uint32_t* __restrict__ xt,
    const uint32_t* __restrict__ wq, const uint32_t* __restrict__ wk, const uint32_t* __restrict__ wv,
    float* __restrict__ q, float* __restrict__ k, float* __restrict__ v)
{
    extern __shared__ uint32_t sh[];
    int bx = blockIdx.x;
    const uint32_t* B;
    float* C;
    int col0, N;
    if (bx < 32)      { B = wq; C = q; col0 = bx * 128;        N = HQN * DD; }
    else if (bx < 40) { B = wk; C = k; col0 = (bx - 32) * 128; N = HKVN * DD; }
    else              { B = wv; C = v; col0 = (bx - 40) * 128; N = HKVN * DD; }
    gemm_body(xt, B, C, N, EE, blockIdx.y * 128, col0, sh, threadIdx.x);
}

// ---------------- l2norm + RoPE: warp per row, table freqs ----------------
__global__ __launch_bounds__(256) void norm_rope2_kernel(float* __restrict__ data, int H, int isQ)
{
    const int gw   = blockIdx.x * 8 + (threadIdx.x >> 5);
    const int lane = threadIdx.x & 31;
    const int s    = (gw / H) % SS;
    float* ptr = data + (size_t)gw * DD;

    float v0 = ptr[lane];
    float v1 = ptr[lane + 32];
    float v2 = ptr[lane + 64];
    float v3 = ptr[lane + 96];

    float ss = v0 * v0 + v1 * v1 + v2 * v2 + v3 * v3;
#pragma unroll
    for (int off = 16; off > 0; off >>= 1)
        ss += __shfl_xor_sync(0xffffffffu, ss, off);

    float inv = rsqrtf(ss * (1.0f / DD) + 1e-6f);
    v0 *= inv; v1 *= inv; v2 *= inv; v3 *= inv;

    float freq0 = g_freq[lane];
    float freq1 = g_freq[lane + 32];
    float s0, c0, s1, c1;
    sincosf((float)s * freq0, &s0, &c0);
    sincosf((float)s * freq1, &s1, &c1);

    float o0 = v0 * c0 - v2 * s0;
    float o2 = v2 * c0 + v0 * s0;
    float o1 = v1 * c1 - v3 * s1;
    float o3 = v3 * c1 + v1 * s1;

    if (isQ) {
        float asc = logf(floorf(((float)s + 1.0f) / 8192.0f) + 1.0f) * 0.1f + 1.0f;
        float sc = 0.08838834764831845f * asc;
        o0 *= sc; o1 *= sc; o2 *= sc; o3 *= sc;
    }
    ptr[lane]      = o0;
    ptr[lane + 32] = o1;
    ptr[lane + 64] = o2;
    ptr[lane + 96] = o3;
}

// ---------------- tensor-core flash attention: TQ=128, tf32 epilogue ----------------
#define QK_STRIDE 132
#define V_STRIDE  136
#define P_STRIDE  68
__global__ __launch_bounds__(256) void attn_tc_kernel()
{
    extern __shared__ uint32_t smu[];
    uint32_t* sQ = smu;                         // 128 x 132
    uint32_t* sK = sQ + 128 * QK_STRIDE;        // 64 x 132
    uint32_t* sV = sK + 64 * QK_STRIDE;         // 64 x 136
    float*    sP = (float*)(sV + 64 * V_STRIDE);// 128 x 68
    float*    sM = sP + 128 * P_STRIDE;         // 128
    float*    sSum = sM + 128;                  // 128
    float*    sAlpha = sSum + 128;              // 128

    const int b  = blockIdx.z;
    const int h  = blockIdx.y;
    const int q0 = blockIdx.x * TQ;
    const int hk = h / (HQN / HKVN);

    const int tid  = threadIdx.x;
    const int warp = tid >> 5;
    const int lane = tid & 31;
    const int l4   = lane & 3;
    const int l28  = lane >> 2;

    const int wm = warp >> 1;
    const int wn = warp & 1;

#pragma unroll
    for (int i = 0; i < 16; i++) {
        int idx = tid + i * 256;
        int r  = idx >> 5;
        int c4 = (idx & 31) << 2;
        float4 qv = *(const float4*)&g_q[(((size_t)(b * SS + q0 + r)) * HQN + h) * DD + c4];
        sQ[r * QK_STRIDE + c4 + 0] = f2tf32(qv.x);
        sQ[r * QK_STRIDE + c4 + 1] = f2tf32(qv.y);
        sQ[r * QK_STRIDE + c4 + 2] = f2tf32(qv.z);
        sQ[r * QK_STRIDE + c4 + 3] = f2tf32(qv.w);
    }
    if (tid < 128) { sM[tid] = -30000.0f; sSum[tid] = 0.0f; }

    float o[2][8][4];
#pragma unroll
    for (int mt = 0; mt < 2; mt++)
#pragma unroll
        for (int nt = 0; nt < 8; nt++)
#pragma unroll
            for (int r = 0; r < 4; r++) o[mt][nt][r] = 0.0f;

    int jlo = q0 - (WIN - 1); if (jlo < 0) jlo = 0;
    int jt0 = (jlo / TK) * TK;
    int jtmax = q0 + TQ - TK;

    for (int jt = jt0; jt <= jtmax; jt += TK) {
        __syncthreads();

#pragma unroll
        for (int i = 0; i < 8; i++) {
            int idx = tid + i * 256;
            int r  = idx >> 5;
            int c4 = (idx & 31) << 2;
            size_t gbase = (((size_t)(b * SS + jt + r)) * HKVN + hk) * DD + c4;
            float4 kv = *(const float4*)&g_k[gbase];
            sK[r * QK_STRIDE + c4 + 0] = f2tf32(kv.x);
            sK[r * QK_STRIDE + c4 + 1] = f2tf32(kv.y);
            sK[r * QK_STRIDE + c4 + 2] = f2tf32(kv.z);
            sK[r * QK_STRIDE + c4 + 3] = f2tf32(kv.w);
            float4 vv = *(const float4*)&g_v[gbase];
            sV[r * V_STRIDE + c4 + 0] = f2tf32(vv.x);
            sV[r * V_STRIDE + c4 + 1] = f2tf32(vv.y);
            sV[r * V_STRIDE + c4 + 2] = f2tf32(vv.z);
            sV[r * V_STRIDE + c4 + 3] = f2tf32(vv.w);
        }
        __syncthreads();

        {
            const int sm0 = wm * 32;
            const int sn0 = wn * 32;
            float acc[2][4][4];
#pragma unroll
            for (int mt = 0; mt < 2; mt++)
#pragma unroll
                for (int nt = 0; nt < 4; nt++)
#pragma unroll
                    for (int r = 0; r < 4; r++) acc[mt][nt][r] = 0.0f;

#pragma unroll
            for (int ks = 0; ks < 16; ks++) {
                const int k0 = ks * 8;
                uint32_t bf[4][2];
#pragma unroll
                for (int nt = 0; nt < 4; nt++) {
                    int n = sn0 + nt * 8 + l28;
                    bf[nt][0] = sK[n * QK_STRIDE + k0 + l4];
                    bf[nt][1] = sK[n * QK_STRIDE + k0 + 4 + l4];
                }
#pragma unroll
                for (int mt = 0; mt < 2; mt++) {
                    int m = sm0 + mt * 16 + l28;
                    uint32_t af[4];
                    af[0] = sQ[m * QK_STRIDE + k0 + l4];
                    af[1] = sQ[(m + 8) * QK_STRIDE + k0 + l4];
                    af[2] = sQ[m * QK_STRIDE + k0 + 4 + l4];
                    af[3] = sQ[(m + 8) * QK_STRIDE + k0 + 4 + l4];
#pragma unroll
                    for (int nt = 0; nt < 4; nt++)
                        mma_tf32(acc[mt][nt], af, bf[nt]);
                }
            }

#pragma unroll
            for (int mt = 0; mt < 2; mt++) {
#pragma unroll
                for (int nt = 0; nt < 4; nt++) {
#pragma unroll
                    for (int r = 0; r < 4; r++) {
                        int lrow = sm0 + mt * 16 + l28 + ((r >> 1) << 3);
                        int lcol = sn0 + nt * 8 + (l4 << 1) + (r & 1);
                        int i = q0 + lrow;
                        int j = jt + lcol;
                        float lg = 50.0f * tanhf(acc[mt][nt][r] * 0.02f);
                        bool valid = (j <= i) && (i - j < WIN);
                        sP[lrow * P_STRIDE + lcol] = valid ? lg : -30000.0f;
                    }
                }
            }
        }
        __syncthreads();

        if (tid < 128) {
            float tm = -30000.0f;
            for (int jj = 0; jj < TK; jj++) {
                int j = (jj + tid) & 63;
                tm = fmaxf(tm, sP[tid * P_STRIDE + j]);
            }
            float mo = sM[tid];
            float mn = fmaxf(mo, tm);
            float alpha = __expf(mo - mn);
            float rs = 0.0f;
            for (int jj = 0; jj < TK; jj++) {
                int j = (jj + tid) & 63;
                float lv = sP[tid * P_STRIDE + j];
                float p = (lv > -20000.0f) ? __expf(lv - mn) : 0.0f;
                sP[tid * P_STRIDE + j] = p;
                rs += p;
            }
            sSum[tid] = sSum[tid] * alpha + rs;
            sM[tid] = mn;
            sAlpha[tid] = alpha;
        }
        __syncthreads();

        {
            const int om0 = wm * 32;
            const int on0 = wn * 64;
#pragma unroll
            for (int mt = 0; mt < 2; mt++) {
                float a_lo = sAlpha[om0 + mt * 16 + l28];
                float a_hi = sAlpha[om0 + mt * 16 + l28 + 8];
#pragma unroll
                for (int nt = 0; nt < 8; nt++) {
                    o[mt][nt][0] *= a_lo; o[mt][nt][1] *= a_lo;
                    o[mt][nt][2] *= a_hi; o[mt][nt][3] *= a_hi;
                }
            }
#pragma unroll
            for (int ks = 0; ks < 8; ks++) {
                const int jb = ks * 8;
                uint32_t bf[8][2];
#pragma unroll
                for (int nt = 0; nt < 8; nt++) {
                    int n = on0 + nt * 8 + l28;
                    bf[nt][0] = sV[(jb + l4) * V_STRIDE + n];
                    bf[nt][1] = sV[(jb + 4 + l4) * V_STRIDE + n];
                }
#pragma unroll
                for (int mt = 0; mt < 2; mt++) {
                    int m = om0 + mt * 16 + l28;
                    uint32_t af[4];
                    af[0] = f2tf32(sP[m * P_STRIDE + jb + l4]);
                    af[1] = f2tf32(sP[(m + 8) * P_STRIDE + jb + l4]);
                    af[2] = f2tf32(sP[m * P_STRIDE + jb + 4 + l4]);
                    af[3] = f2tf32(sP[(m + 8) * P_STRIDE + jb + 4 + l4]);
#pragma unroll
                    for (int nt = 0; nt < 8; nt++)
                        mma_tf32(o[mt][nt], af, bf[nt]);
                }
            }
        }
    }

    {
        const int om0 = wm * 32;
        const int on0 = wn * 64;
#pragma unroll
        for (int mt = 0; mt < 2; mt++) {
            int rlo = om0 + mt * 16 + l28;
            float inv_lo = 1.0f / sSum[rlo];
            float inv_hi = 1.0f / sSum[rlo + 8];
#pragma unroll
            for (int nt = 0; nt < 8; nt++) {
                int col = on0 + nt * 8 + (l4 << 1);
                size_t base_lo = (((size_t)(b * SS + q0 + rlo)) * HQN + h) * DD + col;
                size_t base_hi = (((size_t)(b * SS + q0 + rlo + 8)) * HQN + h) * DD + col;
                uint2 ulo, uhi;
                ulo.x = f2tf32(o[mt][nt][0] * inv_lo);
                ulo.y = f2tf32(o[mt][nt][1] * inv_lo);
                uhi.x = f2tf32(o[mt][nt][2] * inv_hi);
                uhi.y = f2tf32(o[mt][nt][3] * inv_hi);
                *(uint2*)&g_attnt[base_lo] = ulo;
                *(uint2*)&g_attnt[base_hi] = uhi;
            }
        }
    }
}

// ---------------- launch ----------------
extern "C" void kernel_launch(void* const* d_in, const int* in_sizes, int n_in,
                              void* d_out, int out_size)
{
    const float* x  = (const float*)d_in[0];
    const float* Wq = (const float*)d_in[1];
    const float* Wk = (const float*)d_in[2];
    const float* Wv = (const float*)d_in[3];
    const float* Wo = (const float*)d_in[4];
    float* out = (float*)d_out;

    float *q, *k, *v;
    uint32_t *xt, *wqt, *wkt, *wvt, *wot, *attnt;
    cudaGetSymbolAddress((void**)&q,    g_q);
    cudaGetSymbolAddress((void**)&k,    g_k);
    cudaGetSymbolAddress((void**)&v,    g_v);
    cudaGetSymbolAddress((void**)&xt,   g_xt);
    cudaGetSymbolAddress((void**)&wqt,  g_wqt);
    cudaGetSymbolAddress((void**)&wkt,  g_wkt);
    cudaGetSymbolAddress((void**)&wvt,  g_wvt);
    cudaGetSymbolAddress((void**)&wot,  g_wot);
    cudaGetSymbolAddress((void**)&attnt,g_attnt);

    const size_t NBIG = (size_t)NROWS * EE;
    const size_t NSML = (size_t)EE * HKVN * DD;

    init_freq_kernel<<<1, 64>>>();

    cvt_tf32_kernel<<<(int)(NBIG / 1024), 256>>>(x,  xt);
    cvt_tf32_kernel<<<(int)(NBIG / 1024), 256>>>(Wq, wqt);
    cvt_tf32_kernel<<<(int)(NSML / 1024), 256>>>(Wk, wkt);
    cvt_tf32_kernel<<<(int)(NSML / 1024), 256>>>(Wv, wvt);
    cvt_tf32_kernel<<<(int)(NBIG / 1024), 256>>>(Wo, wot);

    cudaFuncSetAttribute(qkv_gemm_kernel,  cudaFuncAttributeMaxDynamicSharedMemorySize, GEMM_SMEM);
    cudaFuncSetAttribute(gemm_tf32p_kernel, cudaFuncAttributeMaxDynamicSharedMemorySize, GEMM_SMEM);

    // fused QKV projection (one launch: 48 column blocks x 32 row blocks)
    qkv_gemm_kernel<<<dim3(48, NROWS / 128), 256, GEMM_SMEM>>>(xt, wqt, wkt, wvt, q, k, v);

    // l2norm + rope
    norm_rope2_kernel<<<NROWS * HQN / 8, 256>>>(q, HQN, 1);
    norm_rope2_kernel<<<NROWS * HKVN / 8, 256>>>(k, HKVN, 0);

    // attention (TQ=128)
    const int att_smem = (128 * QK_STRIDE + 64 * QK_STRIDE + 64 * V_STRIDE) * 4
                       + (128 * P_STRIDE + 3 * 128) * 4;
    cudaFuncSetAttribute(attn_tc_kernel, cudaFuncAttributeMaxDynamicSharedMemorySize, att_smem);
    attn_tc_kernel<<<dim3(SS / TQ, HQN, BB), 256, att_smem>>>();

    // output projection
    gemm_tf32p_kernel<<<dim3(EE / 128, NROWS / 128), 256, GEMM_SMEM>>>(attnt, wot, out, NROWS, EE, HQN * DD);
}

// round 17
// speedup vs baseline: 1.7002x; 1.3290x over previous
#include <cuda_runtime.h>
#include <cuda_fp16.h>
#include <math.h>
#include <stdint.h>

#define BB 2
#define SS 2048
#define EE 4096
#define HQN 32
#define HKVN 8
#define DD 128
#define NROWS (BB*SS)      // 4096
#define WIN 1024
#define TQ 128
#define TK 64

// ---------------- scratch ----------------
__device__ float g_q[(size_t)NROWS * HQN * DD];
__device__ float g_k[(size_t)NROWS * HKVN * DD];
__device__ float g_v[(size_t)NROWS * HKVN * DD];
__device__ __half g_xh  [(size_t)NROWS * EE];           // x fp16, [M][K]
__device__ __half g_wqh [(size_t)EE * HQN * DD];        // Wq^T fp16, [4096][4096]
__device__ __half g_wkh [(size_t)EE * HKVN * DD];       // Wk^T fp16, [1024][4096]
__device__ __half g_wvh [(size_t)EE * HKVN * DD];       // Wv^T fp16, [1024][4096]
__device__ __half g_woh [(size_t)HQN * DD * EE];        // Wo^T fp16, [4096][4096]
__device__ __half g_attnh[(size_t)NROWS * HQN * DD];    // attn fp16, [M][4096]
__device__ float g_freq[64];

// ---------------- helpers ----------------
__device__ __forceinline__ uint32_t f2tf32(float f) {
    uint32_t u;
    asm("cvt.rna.tf32.f32 %0, %1;" : "=r"(u) : "f"(f));
    return u;
}

__device__ __forceinline__ void mma_tf32(float c[4], const uint32_t a[4], const uint32_t b[2]) {
    asm volatile(
        "mma.sync.aligned.m16n8k8.row.col.f32.tf32.tf32.f32 "
        "{%0,%1,%2,%3}, {%4,%5,%6,%7}, {%8,%9}, {%0,%1,%2,%3};\n"
        : "+f"(c[0]), "+f"(c[1]), "+f"(c[2]), "+f"(c[3])
        : "r"(a[0]), "r"(a[1]), "r"(a[2]), "r"(a[3]), "r"(b[0]), "r"(b[1]));
}

// fp16 m16n8k16, fp32 accum
__device__ __forceinline__ void mma_f16(float c[4], const uint32_t a[4], const uint32_t b[2]) {
    asm volatile(
        "mma.sync.aligned.m16n8k16.row.col.f32.f16.f16.f32 "
        "{%0,%1,%2,%3}, {%4,%5,%6,%7}, {%8,%9}, {%0,%1,%2,%3};\n"
        : "+f"(c[0]), "+f"(c[1]), "+f"(c[2]), "+f"(c[3])
        : "r"(a[0]), "r"(a[1]), "r"(a[2]), "r"(a[3]), "r"(b[0]), "r"(b[1]));
}

__device__ __forceinline__ void cp16(void* sdst, const void* gsrc) {
    uint32_t sa = (uint32_t)__cvta_generic_to_shared(sdst);
    asm volatile("cp.async.cg.shared.global [%0], [%1], 16;\n" :: "r"(sa), "l"(gsrc));
}

// ---------------- init: rope freq table ----------------
__global__ void init_kernel()
{
    int t = threadIdx.x;
    if (t < 64) g_freq[t] = (float)exp(-(double)t * (9.210340371976184 / 64.0));
}

// ---------------- fp32 -> fp16 row-major (for x) ----------------
__global__ __launch_bounds__(256) void cvt_h_kernel(const float* __restrict__ in,
                                                    __half* __restrict__ out)
{
    size_t i = ((size_t)blockIdx.x * 256 + threadIdx.x) * 4;
    float4 v = *(const float4*)(in + i);
    __half2 h0 = __floats2half2_rn(v.x, v.y);
    __half2 h1 = __floats2half2_rn(v.z, v.w);
    *(__half2*)(out + i)     = h0;
    *(__half2*)(out + i + 2) = h1;
}

// ---------------- fp32 [K][N] -> fp16 [N][K] transpose ----------------
__global__ void cvtT_h_kernel(const float* __restrict__ in, __half* __restrict__ out, int K, int N)
{
    __shared__ float t[32][33];
    int n0 = blockIdx.x * 32, k0 = blockIdx.y * 32;
#pragma unroll
    for (int i = 0; i < 4; i++) {
        int k = threadIdx.y + i * 8;
        t[k][threadIdx.x] = in[(size_t)(k0 + k) * N + n0 + threadIdx.x];
    }
    __syncthreads();
#pragma unroll
    for (int i = 0; i < 4; i++) {
        int n = threadIdx.y + i * 8;
        out[(size_t)(n0 + n) * K + k0 + threadIdx.x] = __float2half(t[threadIdx.x][n]);
    }
}

// ================= fp16 GEMM: C[M x N] = A[M][K] * BT[N][K]^T =================
// 128x128 tile, K-chunk 32 halves, 2-stage cp.async, 256 thr (8 warps, warp 64x32), 2 CTA/SM.
#define H_ST 20                     // u32 (half2) per smem row: 16 data + 4 pad
#define H_STG (128 * H_ST)          // u32 per stage (A or B)
#define H_SMEM (4 * H_STG * 4)      // 2 stages x (A+B) = 40960 bytes

__device__ __forceinline__ void h_fill(
    const __half* __restrict__ A, const __half* __restrict__ BT,
    uint32_t* __restrict__ as, uint32_t* __restrict__ bs,
    int row0, int col0, int k0, int K, int tid)
{
#pragma unroll
    for (int it = 0; it < 2; it++) {
        int idx = tid + it * 256;                // 512 chunks: 128 rows x 4 (16B each)
        int r = idx >> 2, ch = idx & 3;
        cp16(as + r * H_ST + ch * 4, A + (size_t)(row0 + r) * K + k0 + ch * 8);
    }
#pragma unroll
    for (int it = 0; it < 2; it++) {
        int idx = tid + it * 256;
        int r = idx >> 2, ch = idx & 3;
        cp16(bs + r * H_ST + ch * 4, BT + (size_t)(col0 + r) * K + k0 + ch * 8);
    }
    asm volatile("cp.async.commit_group;\n" ::: "memory");
}

__device__ void h_gemm_body(const __half* __restrict__ A, const __half* __restrict__ BT,
                            float* __restrict__ C, int K, int N, int row0, int col0, uint32_t* sh)
{
    uint32_t* As = sh;                  // 2 x [128][H_ST]
    uint32_t* Bs = sh + 2 * H_STG;      // 2 x [128][H_ST]

    const int tid  = threadIdx.x;
    const int warp = tid >> 5;
    const int lane = tid & 31;
    const int l4   = lane & 3;
    const int l28  = lane >> 2;
    const int m0 = (warp >> 2) * 64;
    const int n0 = (warp & 3) * 32;

    float cacc[4][4][4];
#pragma unroll
    for (int mt = 0; mt < 4; mt++)
#pragma unroll
        for (int nt = 0; nt < 4; nt++)
#pragma unroll
            for (int r = 0; r < 4; r++) cacc[mt][nt][r] = 0.0f;

    const int T = K >> 5;               // K-chunks of 32 halves
    h_fill(A, BT, As, Bs, row0, col0, 0, K, tid);

    for (int kt = 0; kt < T; kt++) {
        if (kt + 1 < T) {
            h_fill(A, BT, As + ((kt + 1) & 1) * H_STG, Bs + ((kt + 1) & 1) * H_STG,
                   row0, col0, (kt + 1) << 5, K, tid);
            asm volatile("cp.async.wait_group 1;\n" ::: "memory");
        } else {
            asm volatile("cp.async.wait_group 0;\n" ::: "memory");
        }
        __syncthreads();

        const uint32_t* as = As + (kt & 1) * H_STG;
        const uint32_t* bs = Bs + (kt & 1) * H_STG;

#pragma unroll
        for (int ks = 0; ks < 2; ks++) {            // two k16 sub-steps
            const int ko = ks * 8;                  // u32 offset
            uint32_t bf[4][2];
#pragma unroll
            for (int nt = 0; nt < 4; nt++) {
                int n = n0 + nt * 8 + l28;
                bf[nt][0] = bs[n * H_ST + ko + l4];
                bf[nt][1] = bs[n * H_ST + ko + 4 + l4];
            }
#pragma unroll
            for (int mt = 0; mt < 4; mt++) {
                int m = m0 + mt * 16 + l28;
                uint32_t af[4];
                af[0] = as[m * H_ST + ko + l4];
                af[1] = as[(m + 8) * H_ST + ko + l4];
                af[2] = as[m * H_ST + ko + 4 + l4];
                af[3] = as[(m + 8) * H_ST + ko + 4 + l4];
#pragma unroll
                for (int nt = 0; nt < 4; nt++)
                    mma_f16(cacc[mt][nt], af, bf[nt]);
            }
        }
        __syncthreads();
    }

#pragma unroll
    for (int mt = 0; mt < 4; mt++) {
#pragma unroll
        for (int nt = 0; nt < 4; nt++) {
            int row = row0 + m0 + mt * 16 + l28;
            int col = col0 + n0 + nt * 8 + (l4 << 1);
            *(float2*)(C + (size_t)row * N + col)       = make_float2(cacc[mt][nt][0], cacc[mt][nt][1]);
            *(float2*)(C + (size_t)(row + 8) * N + col) = make_float2(cacc[mt][nt][2], cacc[mt][nt][3]);
        }
    }
}

// fused QKV: bx<32 -> q; [32,40) -> k; [40,48) -> v
__global__ __launch_bounds__(256, 2) void h_qkv_kernel()
{
    extern __shared__ uint32_t sh[];
    int bx = blockIdx.x;
    const __half* BT; float* C; int col0, N;
    if (bx < 32)      { BT = g_wqh; C = g_q; col0 = bx * 128;        N = HQN * DD; }
    else if (bx < 40) { BT = g_wkh; C = g_k; col0 = (bx - 32) * 128; N = HKVN * DD; }
    else              { BT = g_wvh; C = g_v; col0 = (bx - 40) * 128; N = HKVN * DD; }
    h_gemm_body(g_xh, BT, C, EE, N, blockIdx.y * 128, col0, sh);
}

__global__ __launch_bounds__(256, 2) void h_o_kernel(float* __restrict__ out)
{
    extern __shared__ uint32_t sh[];
    h_gemm_body(g_attnh, g_woh, out, HQN * DD, EE, blockIdx.y * 128, blockIdx.x * 128, sh);
}

// ---------------- l2norm + RoPE: warp per row, table freqs ----------------
__global__ __launch_bounds__(256) void norm_rope2_kernel(float* __restrict__ data, int H, int isQ)
{
    const int gw   = blockIdx.x * 8 + (threadIdx.x >> 5);
    const int lane = threadIdx.x & 31;
    const int s    = (gw / H) % SS;
    float* ptr = data + (size_t)gw * DD;

    float v0 = ptr[lane];
    float v1 = ptr[lane + 32];
    float v2 = ptr[lane + 64];
    float v3 = ptr[lane + 96];

    float ss = v0 * v0 + v1 * v1 + v2 * v2 + v3 * v3;
#pragma unroll
    for (int off = 16; off > 0; off >>= 1)
        ss += __shfl_xor_sync(0xffffffffu, ss, off);

    float inv = rsqrtf(ss * (1.0f / DD) + 1e-6f);
    v0 *= inv; v1 *= inv; v2 *= inv; v3 *= inv;

    float freq0 = g_freq[lane];
    float freq1 = g_freq[lane + 32];
    float s0, c0, s1, c1;
    sincosf((float)s * freq0, &s0, &c0);
    sincosf((float)s * freq1, &s1, &c1);

    float o0 = v0 * c0 - v2 * s0;
    float o2 = v2 * c0 + v0 * s0;
    float o1 = v1 * c1 - v3 * s1;
    float o3 = v3 * c1 + v1 * s1;

    if (isQ) {
        float asc = logf(floorf(((float)s + 1.0f) / 8192.0f) + 1.0f) * 0.1f + 1.0f;
        float sc = 0.08838834764831845f * asc;
        o0 *= sc; o1 *= sc; o2 *= sc; o3 *= sc;
    }
    ptr[lane]      = o0;
    ptr[lane + 32] = o1;
    ptr[lane + 64] = o2;
    ptr[lane + 96] = o3;
}

// ---------------- tensor-core flash attention: TQ=128, fp16 epilogue ----------------
#define QK_STRIDE 132
#define V_STRIDE  136
#define P_STRIDE  68
__global__ __launch_bounds__(256) void attn_tc_kernel()
{
    extern __shared__ uint32_t smu[];
    uint32_t* sQ = smu;                         // 128 x 132 (tf32)
    uint32_t* sK = sQ + 128 * QK_STRIDE;        // 64 x 132
    uint32_t* sV = sK + 64 * QK_STRIDE;         // 64 x 136
    float*    sP = (float*)(sV + 64 * V_STRIDE);// 128 x 68
    float*    sM = sP + 128 * P_STRIDE;         // 128
    float*    sSum = sM + 128;                  // 128
    float*    sAlpha = sSum + 128;              // 128

    const int b  = blockIdx.z;
    const int h  = blockIdx.y;
    const int q0 = blockIdx.x * TQ;
    const int hk = h / (HQN / HKVN);

    const int tid  = threadIdx.x;
    const int warp = tid >> 5;
    const int lane = tid & 31;
    const int l4   = lane & 3;
    const int l28  = lane >> 2;

    const int wm = warp >> 1;
    const int wn = warp & 1;

#pragma unroll
    for (int i = 0; i < 16; i++) {
        int idx = tid + i * 256;
        int r  = idx >> 5;
        int c4 = (idx & 31) << 2;
        float4 qv = *(const float4*)&g_q[(((size_t)(b * SS + q0 + r)) * HQN + h) * DD + c4];
        sQ[r * QK_STRIDE + c4 + 0] = f2tf32(qv.x);
        sQ[r * QK_STRIDE + c4 + 1] = f2tf32(qv.y);
        sQ[r * QK_STRIDE + c4 + 2] = f2tf32(qv.z);
        sQ[r * QK_STRIDE + c4 + 3] = f2tf32(qv.w);
    }
    if (tid < 128) { sM[tid] = -30000.0f; sSum[tid] = 0.0f; }

    float o[2][8][4];
#pragma unroll
    for (int mt = 0; mt < 2; mt++)
#pragma unroll
        for (int nt = 0; nt < 8; nt++)
#pragma unroll
            for (int r = 0; r < 4; r++) o[mt][nt][r] = 0.0f;

    int jlo = q0 - (WIN - 1); if (jlo < 0) jlo = 0;
    int jt0 = (jlo / TK) * TK;
    int jtmax = q0 + TQ - TK;

    for (int jt = jt0; jt <= jtmax; jt += TK) {
        __syncthreads();

#pragma unroll
        for (int i = 0; i < 8; i++) {
            int idx = tid + i * 256;
            int r  = idx >> 5;
            int c4 = (idx & 31) << 2;
            size_t gbase = (((size_t)(b * SS + jt + r)) * HKVN + hk) * DD + c4;
            float4 kv = *(const float4*)&g_k[gbase];
            sK[r * QK_STRIDE + c4 + 0] = f2tf32(kv.x);
            sK[r * QK_STRIDE + c4 + 1] = f2tf32(kv.y);
            sK[r * QK_STRIDE + c4 + 2] = f2tf32(kv.z);
            sK[r * QK_STRIDE + c4 + 3] = f2tf32(kv.w);
            float4 vv = *(const float4*)&g_v[gbase];
            sV[r * V_STRIDE + c4 + 0] = f2tf32(vv.x);
            sV[r * V_STRIDE + c4 + 1] = f2tf32(vv.y);
            sV[r * V_STRIDE + c4 + 2] = f2tf32(vv.z);
            sV[r * V_STRIDE + c4 + 3] = f2tf32(vv.w);
        }
        __syncthreads();

        {
            const int sm0 = wm * 32;
            const int sn0 = wn * 32;
            float acc[2][4][4];
#pragma unroll
            for (int mt = 0; mt < 2; mt++)
#pragma unroll
                for (int nt = 0; nt < 4; nt++)
#pragma unroll
                    for (int r = 0; r < 4; r++) acc[mt][nt][r] = 0.0f;

#pragma unroll
            for (int ks = 0; ks < 16; ks++) {
                const int k0 = ks * 8;
                uint32_t bf[4][2];
#pragma unroll
                for (int nt = 0; nt < 4; nt++) {
                    int n = sn0 + nt * 8 + l28;
                    bf[nt][0] = sK[n * QK_STRIDE + k0 + l4];
                    bf[nt][1] = sK[n * QK_STRIDE + k0 + 4 + l4];
                }
#pragma unroll
                for (int mt = 0; mt < 2; mt++) {
                    int m = sm0 + mt * 16 + l28;
                    uint32_t af[4];
                    af[0] = sQ[m * QK_STRIDE + k0 + l4];
                    af[1] = sQ[(m + 8) * QK_STRIDE + k0 + l4];
                    af[2] = sQ[m * QK_STRIDE + k0 + 4 + l4];
                    af[3] = sQ[(m + 8) * QK_STRIDE + k0 + 4 + l4];
#pragma unroll
                    for (int nt = 0; nt < 4; nt++)
                        mma_tf32(acc[mt][nt], af, bf[nt]);
                }
            }

#pragma unroll
            for (int mt = 0; mt < 2; mt++) {
#pragma unroll
                for (int nt = 0; nt < 4; nt++) {
#pragma unroll
                    for (int r = 0; r < 4; r++) {
                        int lrow = sm0 + mt * 16 + l28 + ((r >> 1) << 3);
                        int lcol = sn0 + nt * 8 + (l4 << 1) + (r & 1);
                        int i = q0 + lrow;
                        int j = jt + lcol;
                        float lg = 50.0f * tanhf(acc[mt][nt][r] * 0.02f);
                        bool valid = (j <= i) && (i - j < WIN);
                        sP[lrow * P_STRIDE + lcol] = valid ? lg : -30000.0f;
                    }
                }
            }
        }
        __syncthreads();

        if (tid < 128) {
            float tm = -30000.0f;
            for (int jj = 0; jj < TK; jj++) {
                int j = (jj + tid) & 63;
                tm = fmaxf(tm, sP[tid * P_STRIDE + j]);
            }
            float mo = sM[tid];
            float mn = fmaxf(mo, tm);
            float alpha = __expf(mo - mn);
            float rs = 0.0f;
            for (int jj = 0; jj < TK; jj++) {
                int j = (jj + tid) & 63;
                float lv = sP[tid * P_STRIDE + j];
                float p = (lv > -20000.0f) ? __expf(lv - mn) : 0.0f;
                sP[tid * P_STRIDE + j] = p;
                rs += p;
            }
            sSum[tid] = sSum[tid] * alpha + rs;
            sM[tid] = mn;
            sAlpha[tid] = alpha;
        }
        __syncthreads();

        {
            const int om0 = wm * 32;
            const int on0 = wn * 64;
#pragma unroll
            for (int mt = 0; mt < 2; mt++) {
                float a_lo = sAlpha[om0 + mt * 16 + l28];
                float a_hi = sAlpha[om0 + mt * 16 + l28 + 8];
#pragma unroll
                for (int nt = 0; nt < 8; nt++) {
                    o[mt][nt][0] *= a_lo; o[mt][nt][1] *= a_lo;
                    o[mt][nt][2] *= a_hi; o[mt][nt][3] *= a_hi;
                }
            }
#pragma unroll
            for (int ks = 0; ks < 8; ks++) {
                const int jb = ks * 8;
                uint32_t bf[8][2];
#pragma unroll
                for (int nt = 0; nt < 8; nt++) {
                    int n = on0 + nt * 8 + l28;
                    bf[nt][0] = sV[(jb + l4) * V_STRIDE + n];
                    bf[nt][1] = sV[(jb + 4 + l4) * V_STRIDE + n];
                }
#pragma unroll
                for (int mt = 0; mt < 2; mt++) {
                    int m = om0 + mt * 16 + l28;
                    uint32_t af[4];
                    af[0] = f2tf32(sP[m * P_STRIDE + jb + l4]);
                    af[1] = f2tf32(sP[(m + 8) * P_STRIDE + jb + l4]);
                    af[2] = f2tf32(sP[m * P_STRIDE + jb + 4 + l4]);
                    af[3] = f2tf32(sP[(m + 8) * P_STRIDE + jb + 4 + l4]);
#pragma unroll
                    for (int nt = 0; nt < 8; nt++)
                        mma_tf32(o[mt][nt], af, bf[nt]);
                }
            }
        }
    }

    // epilogue: normalize and store fp16 (A operand of out-projection)
    {
        const int om0 = wm * 32;
        const int on0 = wn * 64;
#pragma unroll
        for (int mt = 0; mt < 2; mt++) {
            int rlo = om0 + mt * 16 + l28;
            float inv_lo = 1.0f / sSum[rlo];
            float inv_hi = 1.0f / sSum[rlo + 8];
#pragma unroll
            for (int nt = 0; nt < 8; nt++) {
                int col = on0 + nt * 8 + (l4 << 1);
                size_t base_lo = (((size_t)(b * SS + q0 + rlo)) * HQN + h) * DD + col;
                size_t base_hi = (((size_t)(b * SS + q0 + rlo + 8)) * HQN + h) * DD + col;
                *(__half2*)&g_attnh[base_lo] = __floats2half2_rn(o[mt][nt][0] * inv_lo, o[mt][nt][1] * inv_lo);
                *(__half2*)&g_attnh[base_hi] = __floats2half2_rn(o[mt][nt][2] * inv_hi, o[mt][nt][3] * inv_hi);
            }
        }
    }
}

// ---------------- launch ----------------
extern "C" void kernel_launch(void* const* d_in, const int* in_sizes, int n_in,
                              void* d_out, int out_size)
{
    const float* x  = (const float*)d_in[0];
    const float* Wq = (const float*)d_in[1];
    const float* Wk = (const float*)d_in[2];
    const float* Wv = (const float*)d_in[3];
    const float* Wo = (const float*)d_in[4];
    float* out = (float*)d_out;

    float *q, *k;
    __half *xh;
    cudaGetSymbolAddress((void**)&q,  g_q);
    cudaGetSymbolAddress((void**)&k,  g_k);
    cudaGetSymbolAddress((void**)&xh, g_xh);

    __half *wqh, *wkh, *wvh, *woh;
    cudaGetSymbolAddress((void**)&wqh, g_wqh);
    cudaGetSymbolAddress((void**)&wkh, g_wkh);
    cudaGetSymbolAddress((void**)&wvh, g_wvh);
    cudaGetSymbolAddress((void**)&woh, g_woh);

    const size_t NBIG = (size_t)NROWS * EE;

    init_kernel<<<1, 64>>>();

    // operand prep: x row-major fp16; weights transposed fp16
    cvt_h_kernel<<<(int)(NBIG / 1024), 256>>>(x, xh);
    cvtT_h_kernel<<<dim3(EE / 32, EE / 32), dim3(32, 8)>>>(Wq, wqh, EE, HQN * DD);
    cvtT_h_kernel<<<dim3(HKVN * DD / 32, EE / 32), dim3(32, 8)>>>(Wk, wkh, EE, HKVN * DD);
    cvtT_h_kernel<<<dim3(HKVN * DD / 32, EE / 32), dim3(32, 8)>>>(Wv, wvh, EE, HKVN * DD);
    cvtT_h_kernel<<<dim3(EE / 32, HQN * DD / 32), dim3(32, 8)>>>(Wo, woh, HQN * DD, EE);

    cudaFuncSetAttribute(h_qkv_kernel, cudaFuncAttributeMaxDynamicSharedMemorySize, H_SMEM);
    cudaFuncSetAttribute(h_o_kernel,   cudaFuncAttributeMaxDynamicSharedMemorySize, H_SMEM);

    // fused QKV projection (fp16 tensor cores)
    h_qkv_kernel<<<dim3(48, NROWS / 128), 256, H_SMEM>>>();

    // l2norm + rope
    norm_rope2_kernel<<<NROWS * HQN / 8, 256>>>(q, HQN, 1);
    norm_rope2_kernel<<<NROWS * HKVN / 8, 256>>>(k, HKVN, 0);

    // attention (TQ=128, tf32 internals, fp16 output)
    const int att_smem = (128 * QK_STRIDE + 64 * QK_STRIDE + 64 * V_STRIDE) * 4
                       + (128 * P_STRIDE + 3 * 128) * 4;
    cudaFuncSetAttribute(attn_tc_kernel, cudaFuncAttributeMaxDynamicSharedMemorySize, att_smem);
    attn_tc_kernel<<<dim3(SS / TQ, HQN, BB), 256, att_smem>>>();

    // output projection (fp16 tensor cores)
    h_o_kernel<<<dim3(EE / 128, NROWS / 128), 256, H_SMEM>>>(out);
}